// round 15
// baseline (speedup 1.0000x reference)
#include <cuda_runtime.h>
#include <cuda_bf16.h>
#include <stdint.h>

typedef unsigned long long ull;

#define NP 11
__host__ __device__ constexpr int PL1[NP]={0,0,0,1,1,1,1,2,2,2,2};
__host__ __device__ constexpr int PL2[NP]={0,1,2,0,1,1,2,0,1,2,2};
__host__ __device__ constexpr int PL3[NP]={0,1,2,1,0,2,1,2,1,0,2};
__host__ __device__ constexpr int XOFF[3]={0,1,4};
__host__ __device__ constexpr int CPB[NP]={0,2,14,44,56,74,128,188,218,278,328};
#define C_TOT 478

// l3-groups: G0 (l3=2): paths {2,5,7,10}; G1 (l3=1): {1,3,6,8}; G2 (l3=0): {0,4,9}
__host__ __device__ constexpr int GP[3][4]={{2,5,7,10},{1,3,6,8},{0,4,9,0}};
__host__ __device__ constexpr int GNPx[3]={4,4,3};
__host__ __device__ constexpr int GZT[3]={24,42,128};
__host__ __device__ constexpr int GKO[3]={4,1,0};
// CTAs: G0: ceil(1024/24)=43 ztiles *4 u-splits =172; G1: 25*4=100; G2: 8*4=32 -> 304

// smem byte offsets
#define OFF_C   0        // 478 floats -> 2048
#define OFF_A   2048     // Ahi 128x72 bf16 (stride 144B) = 18432
#define OFF_AL  20480    // Alo 18432
#define OFF_BH  38912    // Bhi 64x72 bf16 = 9216
#define OFF_BL  48128    // Blo 9216
#define OFF_X1  57344    // up to 64 rec * 10 ull = 5120
#define OFF_X2  62464    // up to 1024 rec * 10 ull = 81920
#define SMEM_B  144384

// prepped W: per (g,u,vb) tile: hi 64x64 bf16 dense (8KB) then lo (8KB)
__device__ __align__(16) __nv_bfloat16 g_Wb[3*64*4*2*4096];

// ---------- helpers ----------
__device__ __forceinline__ ull pk(float lo,float hi){ull r;asm("mov.b64 %0,{%1,%2};":"=l"(r):"r"(__float_as_uint(lo)),"r"(__float_as_uint(hi)));return r;}
__device__ __forceinline__ void unpk(ull v,float&lo,float&hi){unsigned a,b;asm("mov.b64 {%0,%1},%2;":"=r"(a),"=r"(b):"l"(v));lo=__uint_as_float(a);hi=__uint_as_float(b);}
__device__ __forceinline__ ull fma2(ull a,ull b,ull c){ull d;asm("fma.rn.f32x2 %0,%1,%2,%3;":"=l"(d):"l"(a),"l"(b),"l"(c));return d;}
__device__ __forceinline__ ull mul2(ull a,ull b){ull d;asm("mul.rn.f32x2 %0,%1,%2;":"=l"(d):"l"(a),"l"(b));return d;}
__device__ __forceinline__ uint32_t s2u32(const void*p){uint32_t a;asm("{ .reg .u64 t; cvta.to.shared.u64 t,%1; cvt.u32.u64 %0,t; }":"=r"(a):"l"(p));return a;}
__device__ __forceinline__ void cpa16(uint32_t d,const void*s){asm volatile("cp.async.cg.shared.global [%0],[%1],16;"::"r"(d),"l"(s));}
__device__ __forceinline__ void cpcommit(){asm volatile("cp.async.commit_group;");}
__device__ __forceinline__ void cpwait0(){asm volatile("cp.async.wait_group 0;":::"memory");}
__device__ __forceinline__ void st16(uint32_t a,unsigned short v){asm volatile("st.shared.u16 [%0],%1;"::"r"(a),"h"(v));}

__device__ __forceinline__ void ldsm4(uint32_t*r,uint32_t a){
    asm volatile("ldmatrix.sync.aligned.m8n8.x4.shared.b16 {%0,%1,%2,%3},[%4];"
        :"=r"(r[0]),"=r"(r[1]),"=r"(r[2]),"=r"(r[3]):"r"(a));
}
__device__ __forceinline__ void mma16816(float*c,const uint32_t*a,uint32_t b0,uint32_t b1){
    asm volatile("mma.sync.aligned.m16n8k16.row.col.f32.bf16.bf16.f32 "
        "{%0,%1,%2,%3},{%4,%5,%6,%7},{%8,%9},{%0,%1,%2,%3};"
        :"+f"(c[0]),"+f"(c[1]),"+f"(c[2]),"+f"(c[3])
        :"r"(a[0]),"r"(a[1]),"r"(a[2]),"r"(a[3]),"r"(b0),"r"(b1));
}

// ---------- prep: W -> bf16 hi/lo dense tiles ----------
__global__ void prep_W(const float* __restrict__ W){
    int idx=blockIdx.x*256+threadIdx.x;   // 3*64*4*64*8 = 393216
    int c8=idx&7, w=(idx>>3)&63, vb=(idx>>9)&3, u=(idx>>11)&63, g=idx>>17;
    __nv_bfloat16 hi[8],lo[8];
#pragma unroll
    for(int j=0;j<8;j++){
        int col=c8*8+j, uvl=col>>2, pg=col&3;
        float val=0.f;
        if(pg<GNPx[g]){int p=GP[g][pg];val=W[(((p<<6)+w)<<12)+(u<<6)+vb*16+uvl];}
        __nv_bfloat16 h=__float2bfloat16(val);
        hi[j]=h; lo[j]=__float2bfloat16(val-__bfloat162float(h));
    }
    char* tb=(char*)g_Wb+(size_t)(((g*64+u)*4+vb))*16384;
    *(uint4*)(tb + w*128 + c8*16)        = *(uint4*)hi;
    *(uint4*)(tb + 8192 + w*128 + c8*16) = *(uint4*)lo;
}

// ---------- Phase A cell: one path -> t -> bf16 hi/lo st16 into A tile ------
template<int P,int ZT>
__device__ __forceinline__ void cellA(const ull*a,const ull*b,const float* __restrict__ cf,
                                      uint32_t ahi,uint32_t alo,int z,int colByte){
    constexpr int L1=PL1[P],L2=PL2[P],L3=PL3[P];
    constexpr int M1=2*L1+1,M2=2*L2+1,M3=2*L3+1;
    constexpr int O1=XOFF[L1],O2=XOFF[L2];
    constexpr int CB=CPB[P],SLOT=M3+(M3&1);
    ull t[M3];
#pragma unroll
    for(int k=0;k<M3;k++)t[k]=0ull;
#pragma unroll
    for(int m=0;m<M1;m++){
        ull am=a[O1+m];
#pragma unroll
        for(int n=0;n<M2;n++){
            ull o=mul2(am,b[O2+n]);
            const float* cc=cf+CB+(m*M2+n)*SLOT;
#pragma unroll
            for(int kk=0;kk<M3/2;kk++){
                float2 c2=*(const float2*)(cc+2*kk);
                t[2*kk]  =fma2(o,pk(c2.x,c2.x),t[2*kk]);
                t[2*kk+1]=fma2(o,pk(c2.y,c2.y),t[2*kk+1]);
            }
            float cl=cc[M3-1];
            t[M3-1]=fma2(o,pk(cl,cl),t[M3-1]);
        }
    }
#pragma unroll
    for(int k=0;k<M3;k++){
        float f0,f1; unpk(t[k],f0,f1);
        __nv_bfloat16 h0=__float2bfloat16(f0),h1=__float2bfloat16(f1);
        unsigned short h0u=__bfloat16_as_ushort(h0),h1u=__bfloat16_as_ushort(h1);
        unsigned short l0u=__bfloat16_as_ushort(__float2bfloat16(f0-__bfloat162float(h0)));
        unsigned short l1u=__bfloat16_as_ushort(__float2bfloat16(f1-__bfloat162float(h1)));
        uint32_t off=(uint32_t)((k*ZT+z)*144+colByte);
        st16(ahi+off,h0u);     st16(alo+off,l0u);
        st16(ahi+off+144,h1u); st16(alo+off+144,l1u);
    }
}

// ---------- per-group body ----------
template<int G>
__device__ void run(int rb,
        const float*x1_0,const float*x2_0,const float*x1_1,const float*x2_1,
        const float*x1_2,const float*x2_2,const float*const*cps,float*out,char*smem){
    constexpr int ZT=GZT[G], ZP=ZT/2, KO=GKO[G], M3=5-2*G;
    const int ztile=rb>>2, us=rb&3;
    const int zbase=ztile*ZT, ubase=us*16;
    const int tid=threadIdx.x, lane=tid&31, wid=tid>>5;
    const int wm=wid&3, wn=wid>>2;

    float* cf=(float*)(smem+OFF_C);
    ull* x1s=(ull*)(smem+OFF_X1);
    ull* x2s=(ull*)(smem+OFF_X2);
    const uint32_t sb=s2u32(smem);
    const uint32_t sAh=sb+OFF_A, sBh=sb+OFF_BH;

    // stage C
    for(int idx=tid;idx<C_TOT;idx+=256){
        int p=0;
#pragma unroll
        for(int q=1;q<NP;q++) if(idx>=CPB[q]) p=q;
        int off=idx-CPB[p],m3=2*PL3[p]+1,slot=m3+(m3&1);
        int mn=off/slot,k=off%slot;
        cf[idx]=(k<m3)?cps[p][mn*m3+k]:0.f;
    }
    // zero A tiles (pad rows / unused path-slot cols stay 0 forever)
    { ull* az=(ull*)(smem+OFF_A); for(int i=tid;i<4608;i+=256) az[i]=0ull; }
    __syncthreads();

    float acc[2][4][4];
#pragma unroll
    for(int i=0;i<2;i++)
#pragma unroll
    for(int j=0;j<4;j++)
#pragma unroll
    for(int k=0;k<4;k++) acc[i][j][k]=0.f;

    // ldmatrix base addresses (per-lane)
    const uint32_t aA0 = sAh + (uint32_t)(wm*32+(lane&15))*144 + (uint32_t)((lane>>4)*16);
    const uint32_t bA0 = sBh + (uint32_t)(wn*32+(lane&7)+((lane>>4)<<3))*144 + (uint32_t)(((lane>>3)&1)*16);

    for(int vb=0;vb<4;vb++){
        // stage x2 [vl*ZP+zp][10]
        for(int idx=tid;idx<16*ZP*9;idx+=256){
            int rec=idx/9,n=idx%9,vl=rec/ZP,zp=rec%ZP;
            int v=vb*16+vl,z0=zbase+zp*2;
            int za=z0<1024?z0:1023, zb=(z0+1)<1024?z0+1:1023;
            float a,b;
            if(n==0){a=x2_0[za*64+v];b=x2_0[zb*64+v];}
            else if(n<4){a=x2_1[(za*64+v)*3+n-1];b=x2_1[(zb*64+v)*3+n-1];}
            else{a=x2_2[(za*64+v)*5+n-4];b=x2_2[(zb*64+v)*5+n-4];}
            x2s[rec*10+n]=pk(a,b);
        }
        for(int ui=0;ui<16;ui++){
            const int u=ubase+ui;
            // stage x1 [zp][10]
            for(int idx=tid;idx<ZP*9;idx+=256){
                int zp=idx/9,m=idx%9,z0=zbase+zp*2;
                int za=z0<1024?z0:1023, zb=(z0+1)<1024?z0+1:1023;
                float a,b;
                if(m==0){a=x1_0[za*64+u];b=x1_0[zb*64+u];}
                else if(m<4){a=x1_1[(za*64+u)*3+m-1];b=x1_1[(zb*64+u)*3+m-1];}
                else{a=x1_2[(za*64+u)*5+m-4];b=x1_2[(zb*64+u)*5+m-4];}
                x1s[zp*10+m]=pk(a,b);
            }
            __syncthreads();
            // cp.async W tile (hi+lo, dense 128B rows -> padded 144B rows)
            {
                const char* base=(const char*)g_Wb+(size_t)(((G*64+u)*4+vb))*16384;
#pragma unroll
                for(int i=0;i<4;i++){
                    int c=tid+i*256;              // 0..1023
                    int sp=c>>9, row=(c>>3)&63, sg=c&7;
                    cpa16(sBh+(uint32_t)(sp*9216+row*144+sg*16),
                          base+sp*8192+row*128+sg*16);
                }
                cpcommit();
            }
            // Phase A: t -> A tiles
            for(int cell=tid;cell<16*ZP;cell+=256){
                int uvl=cell/ZP, zp=cell%ZP, z=zp*2, cb=uvl*8;
                ull a[10],b[10];
                const ulonglong2* ap=(const ulonglong2*)(x1s+zp*10);
                const ulonglong2* bp=(const ulonglong2*)(x2s+cell*10);
#pragma unroll
                for(int i=0;i<5;i++){ulonglong2 qa=ap[i],qb=bp[i];
                    a[2*i]=qa.x;a[2*i+1]=qa.y;b[2*i]=qb.x;b[2*i+1]=qb.y;}
                if(G==0){
                    cellA<2 ,ZT>(a,b,cf,sAh,sAh+18432,z,cb+0);
                    cellA<5 ,ZT>(a,b,cf,sAh,sAh+18432,z,cb+2);
                    cellA<7 ,ZT>(a,b,cf,sAh,sAh+18432,z,cb+4);
                    cellA<10,ZT>(a,b,cf,sAh,sAh+18432,z,cb+6);
                } else if(G==1){
                    cellA<1,ZT>(a,b,cf,sAh,sAh+18432,z,cb+0);
                    cellA<3,ZT>(a,b,cf,sAh,sAh+18432,z,cb+2);
                    cellA<6,ZT>(a,b,cf,sAh,sAh+18432,z,cb+4);
                    cellA<8,ZT>(a,b,cf,sAh,sAh+18432,z,cb+6);
                } else {
                    cellA<0,ZT>(a,b,cf,sAh,sAh+18432,z,cb+0);
                    cellA<4,ZT>(a,b,cf,sAh,sAh+18432,z,cb+2);
                    cellA<9,ZT>(a,b,cf,sAh,sAh+18432,z,cb+4);
                }
            }
            cpwait0();
            __syncthreads();
            // MMA: 4 k-steps x (2 m-tiles x 4 n-tiles) x 3 terms
#pragma unroll
            for(int ks=0;ks<4;ks++){
                uint32_t ah[8],al[8],bh[8],bl[8];
                ldsm4(ah+0, aA0+ks*32);
                ldsm4(ah+4, aA0+2304+ks*32);
                ldsm4(al+0, aA0+18432+ks*32);
                ldsm4(al+4, aA0+18432+2304+ks*32);
                ldsm4(bh+0, bA0+ks*32);
                ldsm4(bh+4, bA0+2304+ks*32);
                ldsm4(bl+0, bA0+9216+ks*32);
                ldsm4(bl+4, bA0+9216+2304+ks*32);
#pragma unroll
                for(int mt=0;mt<2;mt++)
#pragma unroll
                for(int nt=0;nt<4;nt++){
                    int e=(nt>>1)*4+(nt&1)*2;
                    mma16816(acc[mt][nt], ah+4*mt, bh[e],bh[e+1]);
                    mma16816(acc[mt][nt], ah+4*mt, bl[e],bl[e+1]);
                    mma16816(acc[mt][nt], al+4*mt, bh[e],bh[e+1]);
                }
            }
            __syncthreads();
        }
    }
    // epilogue: acc frag -> out (atomicAdd across 4 u-split CTAs)
#pragma unroll
    for(int mt=0;mt<2;mt++)
#pragma unroll
    for(int nt=0;nt<4;nt++){
        int R0=wm*32+mt*16+(lane>>2);
        int C0=wn*32+nt*8+(lane&3)*2;
#pragma unroll
        for(int e=0;e<4;e++){
            int r=R0+(e>>1)*8, w=C0+(e&1);
            int k=r/ZT, zl=r%ZT, z=zbase+zl;
            if(k<M3 && z<1024)
                atomicAdd(out+(size_t)(z*64+w)*9+KO+k, acc[mt][nt][e]);
        }
    }
}

// ---------- main kernel ----------
__global__ void __launch_bounds__(256,1)
tp_mma(const float* x1_0,const float* x2_0,const float* x1_1,const float* x2_1,
       const float* x1_2,const float* x2_2,
       const float* C0,const float* C1,const float* C2,const float* C3,const float* C4,
       const float* C5,const float* C6,const float* C7,const float* C8,const float* C9,
       const float* C10,float* out){
    extern __shared__ char smem[];
    const float* cps[NP]={C0,C1,C2,C3,C4,C5,C6,C7,C8,C9,C10};
    int bid=blockIdx.x;
    if(bid<172)      run<0>(bid,     x1_0,x2_0,x1_1,x2_1,x1_2,x2_2,cps,out,smem);
    else if(bid<272) run<1>(bid-172, x1_0,x2_0,x1_1,x2_1,x1_2,x2_2,cps,out,smem);
    else             run<2>(bid-272, x1_0,x2_0,x1_1,x2_1,x1_2,x2_2,cps,out,smem);
}

// ---------------------------------------------------------------------------
extern "C" void kernel_launch(void* const* d_in, const int* in_sizes, int n_in,
                              void* d_out, int out_size) {
    (void)in_sizes;(void)n_in;
    const float* x1_0=(const float*)d_in[0];
    const float* x2_0=(const float*)d_in[1];
    const float* x1_1=(const float*)d_in[2];
    const float* x2_1=(const float*)d_in[3];
    const float* x1_2=(const float*)d_in[4];
    const float* x2_2=(const float*)d_in[5];
    const float* W   =(const float*)d_in[6];
    float* out=(float*)d_out;

    cudaFuncSetAttribute(tp_mma, cudaFuncAttributeMaxDynamicSharedMemorySize, SMEM_B);

    cudaMemsetAsync(d_out,0,(size_t)out_size*sizeof(float),0);
    prep_W<<<1536,256>>>(W);
    tp_mma<<<304,256,SMEM_B>>>(x1_0,x2_0,x1_1,x2_1,x1_2,x2_2,
        (const float*)d_in[7],(const float*)d_in[8],(const float*)d_in[9],
        (const float*)d_in[10],(const float*)d_in[11],(const float*)d_in[12],
        (const float*)d_in[13],(const float*)d_in[14],(const float*)d_in[15],
        (const float*)d_in[16],(const float*)d_in[17],out);
}

// round 17
// speedup vs baseline: 1.0797x; 1.0797x over previous
#include <cuda_runtime.h>
#include <cuda_bf16.h>
#include <stdint.h>

typedef unsigned long long ull;

#define NP 11
__host__ __device__ constexpr int PL1[NP]={0,0,0,1,1,1,1,2,2,2,2};
__host__ __device__ constexpr int PL2[NP]={0,1,2,0,1,1,2,0,1,2,2};
__host__ __device__ constexpr int PL3[NP]={0,1,2,1,0,2,1,2,1,0,2};
__host__ __device__ constexpr int XOFF[3]={0,1,4};
__host__ __device__ constexpr int CPB[NP]={0,2,14,44,56,74,128,188,218,278,328};
#define C_TOT 478

__host__ __device__ constexpr int GP[3][4]={{2,5,7,10},{1,3,6,8},{0,4,9,0}};
__host__ __device__ constexpr int GNPx[3]={4,4,3};
__host__ __device__ constexpr int GZT[3]={24,42,128};
__host__ __device__ constexpr int GKO[3]={4,1,0};
// CTAs: G0 43*4=172, G1 25*4=100, G2 8*4=32 -> 304

// smem byte offsets
#define OFF_C   0
#define OFF_A   2048     // Ahi 128x144B = 18432
#define OFF_AL  20480    // Alo 18432
#define OFF_BH  38912    // Bhi 9216
#define OFF_BL  48128    // Blo 9216
#define OFF_X1  57344    // 64 rec * 11 ull
#define OFF_X2  62976    // 512 rec * 11 ull
#define SMEM_B  108032   // -> 2 CTAs/SM

__device__ __align__(16) __nv_bfloat16 g_Wb[3*64*4*2*4096];

// ---------- helpers ----------
__device__ __forceinline__ ull pk(float lo,float hi){ull r;asm("mov.b64 %0,{%1,%2};":"=l"(r):"r"(__float_as_uint(lo)),"r"(__float_as_uint(hi)));return r;}
__device__ __forceinline__ void unpk(ull v,float&lo,float&hi){unsigned a,b;asm("mov.b64 {%0,%1},%2;":"=r"(a),"=r"(b):"l"(v));lo=__uint_as_float(a);hi=__uint_as_float(b);}
__device__ __forceinline__ ull fma2(ull a,ull b,ull c){ull d;asm("fma.rn.f32x2 %0,%1,%2,%3;":"=l"(d):"l"(a),"l"(b),"l"(c));return d;}
__device__ __forceinline__ ull mul2(ull a,ull b){ull d;asm("mul.rn.f32x2 %0,%1,%2;":"=l"(d):"l"(a),"l"(b));return d;}
__device__ __forceinline__ uint32_t s2u32(const void*p){uint32_t a;asm("{ .reg .u64 t; cvta.to.shared.u64 t,%1; cvt.u32.u64 %0,t; }":"=r"(a):"l"(p));return a;}
__device__ __forceinline__ void cpa16(uint32_t d,const void*s){asm volatile("cp.async.cg.shared.global [%0],[%1],16;"::"r"(d),"l"(s));}
__device__ __forceinline__ void cpcommit(){asm volatile("cp.async.commit_group;");}
__device__ __forceinline__ void cpwait0(){asm volatile("cp.async.wait_group 0;":::"memory");}
__device__ __forceinline__ void ldsm4(uint32_t*r,uint32_t a){
    asm volatile("ldmatrix.sync.aligned.m8n8.x4.shared.b16 {%0,%1,%2,%3},[%4];"
        :"=r"(r[0]),"=r"(r[1]),"=r"(r[2]),"=r"(r[3]):"r"(a));
}
__device__ __forceinline__ void mma16816(float*c,const uint32_t*a,uint32_t b0,uint32_t b1){
    asm volatile("mma.sync.aligned.m16n8k16.row.col.f32.bf16.bf16.f32 "
        "{%0,%1,%2,%3},{%4,%5,%6,%7},{%8,%9},{%0,%1,%2,%3};"
        :"+f"(c[0]),"+f"(c[1]),"+f"(c[2]),"+f"(c[3])
        :"r"(a[0]),"r"(a[1]),"r"(a[2]),"r"(a[3]),"r"(b0),"r"(b1));
}
// pack 4 hi bf16 of a row + residual row; two 8B smem stores
__device__ __forceinline__ void storeRow(uint32_t addr,float f0,float f1,float f2,float f3){
    uint32_t pA,pB,qA,qB;
    asm("cvt.rn.bf16x2.f32 %0,%1,%2;":"=r"(pA):"f"(f1),"f"(f0));
    asm("cvt.rn.bf16x2.f32 %0,%1,%2;":"=r"(pB):"f"(f3),"f"(f2));
    asm volatile("st.shared.v2.b32 [%0],{%1,%2};"::"r"(addr),"r"(pA),"r"(pB));
    float r0=f0-__uint_as_float(pA<<16), r1=f1-__uint_as_float(pA&0xFFFF0000u);
    float r2=f2-__uint_as_float(pB<<16), r3=f3-__uint_as_float(pB&0xFFFF0000u);
    asm("cvt.rn.bf16x2.f32 %0,%1,%2;":"=r"(qA):"f"(r1),"f"(r0));
    asm("cvt.rn.bf16x2.f32 %0,%1,%2;":"=r"(qB):"f"(r3),"f"(r2));
    asm volatile("st.shared.v2.b32 [%0],{%1,%2};"::"r"(addr+18432),"r"(qA),"r"(qB));
}
// FIXED: scalar 8B loads (records are 8B-aligned only, stride 11 ull)
#define LDP(dst,src,i) { (dst)[i]=(src)[i]; (dst)[(i)+1]=(src)[(i)+1]; }

// ---------- prep: W -> bf16 hi/lo dense tiles ----------
template<int G>
__global__ void prep_W(const float* __restrict__ W){
    constexpr int VC=(G==2)?8:16, KC=4*VC, KC8=KC/8, NVB=64/VC;
    int idx=blockIdx.x*256+threadIdx.x;
    int c8=idx%KC8, w=(idx/KC8)&63, vb=(idx/(KC8*64))%NVB, u=idx/(KC8*64*NVB);
    __nv_bfloat16 hi[8],lo[8];
#pragma unroll
    for(int j=0;j<8;j++){
        int col=c8*8+j, uvl=col>>2, pg=col&3, v=vb*VC+uvl;
        float val=0.f;
        if(pg<GNPx[G]){int p=GP[G][pg];val=W[(((p<<6)+w)<<12)+(u<<6)+v];}
        __nv_bfloat16 h=__float2bfloat16(val);
        hi[j]=h; lo[j]=__float2bfloat16(val-__bfloat162float(h));
    }
    size_t tb=(G==0)?(size_t)(u*4+vb)*16384
             :(G==1)?4194304u+(size_t)(u*4+vb)*16384
             :8388608u+(size_t)(u*8+vb)*8192;
    char* p=(char*)g_Wb+tb;
    *(uint4*)(p + w*(KC*2) + c8*16)          = *(uint4*)hi;
    *(uint4*)(p + KC*128 + w*(KC*2) + c8*16) = *(uint4*)lo;
}

// ---------- Phase A: one path's t (register result) ----------
template<int P>
__device__ __forceinline__ void pathT(const ull*a,const ull*b,const float* __restrict__ cf,ull*t){
    constexpr int L1=PL1[P],L2=PL2[P],L3=PL3[P];
    constexpr int M1=2*L1+1,M2=2*L2+1,M3=2*L3+1;
    constexpr int O1=XOFF[L1],O2=XOFF[L2];
    constexpr int CB=CPB[P],SLOT=M3+(M3&1);
#pragma unroll
    for(int k=0;k<M3;k++)t[k]=0ull;
#pragma unroll
    for(int m=0;m<M1;m++){
        ull am=a[O1+m];
#pragma unroll
        for(int n=0;n<M2;n++){
            ull o=mul2(am,b[O2+n]);
            const float* cc=cf+CB+(m*M2+n)*SLOT;
#pragma unroll
            for(int kk=0;kk<M3/2;kk++){
                float2 c2=*(const float2*)(cc+2*kk);
                t[2*kk]  =fma2(o,pk(c2.x,c2.x),t[2*kk]);
                t[2*kk+1]=fma2(o,pk(c2.y,c2.y),t[2*kk+1]);
            }
            float cl=cc[M3-1];
            t[M3-1]=fma2(o,pk(cl,cl),t[M3-1]);
        }
    }
}

// ---------- per-group body ----------
template<int G>
__device__ void run(int rb,
        const float*x1_0,const float*x2_0,const float*x1_1,const float*x2_1,
        const float*x1_2,const float*x2_2,const float*const*cps,float*out,char*smem){
    constexpr int ZT=GZT[G], ZP=ZT/2, KO=GKO[G], M3=5-2*G;
    constexpr int VC=(G==2)?8:16, KC=4*VC, KS=KC/16, KC8=KC/8, NVB=64/VC;
    const int ztile=rb>>2, us=rb&3;
    const int zbase=ztile*ZT, ubase=us*16;
    const int tid=threadIdx.x, lane=tid&31, wm=tid>>5;

    float* cf=(float*)(smem+OFF_C);
    ull* x1s=(ull*)(smem+OFF_X1);
    ull* x2s=(ull*)(smem+OFF_X2);
    const uint32_t sb=s2u32(smem);

    for(int idx=tid;idx<C_TOT;idx+=128){
        int p=0;
#pragma unroll
        for(int q=1;q<NP;q++) if(idx>=CPB[q]) p=q;
        int off=idx-CPB[p],m3=2*PL3[p]+1,slot=m3+(m3&1);
        int mn=off/slot,k=off%slot;
        cf[idx]=(k<m3)?cps[p][mn*m3+k]:0.f;
    }
    { ull* az=(ull*)(smem+OFF_A); for(int i=tid;i<4608;i+=128) az[i]=0ull; }
    __syncthreads();

    float acc[2][8][4];
#pragma unroll
    for(int i=0;i<2;i++)
#pragma unroll
    for(int j=0;j<8;j++)
#pragma unroll
    for(int k=0;k<4;k++) acc[i][j][k]=0.f;

    const uint32_t aAddr = sb+OFF_A  + (uint32_t)((wm*32+(lane&15))*144) + (uint32_t)((lane>>4)*16);
    const uint32_t bAddr = sb+OFF_BH + (uint32_t)(((lane&7)+((lane>>4)<<3))*144) + (uint32_t)(((lane>>3)&1)*16);

    for(int vb=0;vb<NVB;vb++){
        for(int idx=tid;idx<VC*ZP*9;idx+=128){
            int rec=idx/9,n=idx%9,zp=rec/VC,vl=rec%VC;
            int v=vb*VC+vl,z0=zbase+zp*2;
            int za=z0<1024?z0:1023, zb=(z0+1)<1024?z0+1:1023;
            float a,b;
            if(n==0){a=x2_0[za*64+v];b=x2_0[zb*64+v];}
            else if(n<4){a=x2_1[(za*64+v)*3+n-1];b=x2_1[(zb*64+v)*3+n-1];}
            else{a=x2_2[(za*64+v)*5+n-4];b=x2_2[(zb*64+v)*5+n-4];}
            x2s[rec*11+n]=pk(a,b);
        }
        for(int ui=0;ui<16;ui++){
            const int u=ubase+ui;
            for(int idx=tid;idx<ZP*9;idx+=128){
                int zp=idx/9,m=idx%9,z0=zbase+zp*2;
                int za=z0<1024?z0:1023, zb=(z0+1)<1024?z0+1:1023;
                float a,b;
                if(m==0){a=x1_0[za*64+u];b=x1_0[zb*64+u];}
                else if(m<4){a=x1_1[(za*64+u)*3+m-1];b=x1_1[(zb*64+u)*3+m-1];}
                else{a=x1_2[(za*64+u)*5+m-4];b=x1_2[(zb*64+u)*5+m-4];}
                x1s[zp*11+m]=pk(a,b);
            }
            __syncthreads();
            {
                const char* wt=(const char*)g_Wb+((G==0)?(size_t)(u*4+vb)*16384
                    :(G==1)?4194304u+(size_t)(u*4+vb)*16384
                    :8388608u+(size_t)(u*8+vb)*8192);
#pragma unroll
                for(int i=0;i<KC8;i++){
                    int c=tid+i*128;
                    int sp=c/(64*KC8), r=c%(64*KC8), row=r/KC8, sg=r%KC8;
                    cpa16(sb+OFF_BH+(uint32_t)(sp*9216+row*144+sg*16),
                          wt+sp*(KC*128)+row*(KC*2)+sg*16);
                }
                cpcommit();
            }
            for(int cell=tid;cell<VC*ZP;cell+=128){
                int zp=cell/VC, uvl=cell%VC, z=zp*2;
                ull a[10],b[10];
                const ull* ap=x1s+zp*11;
                const ull* bp=x2s+cell*11;
#pragma unroll
                for(int i=0;i<4;i+=2){LDP(a,ap,i);LDP(b,bp,i);}
                LDP(a,ap,4);LDP(a,ap,6);LDP(b,bp,4);LDP(b,bp,6);
                a[8]=ap[8];b[8]=bp[8];
                uint32_t base=sb+OFF_A+(uint32_t)(z*144+uvl*8);
                if(G==0){
                    ull t0[5],t1[5],t2[5],t3[5];
                    pathT<2>(a,b,cf,t0);pathT<5>(a,b,cf,t1);
                    pathT<7>(a,b,cf,t2);pathT<10>(a,b,cf,t3);
#pragma unroll
                    for(int k=0;k<5;k++){
                        float f0a,f0b,f1a,f1b,f2a,f2b,f3a,f3b;
                        unpk(t0[k],f0a,f0b);unpk(t1[k],f1a,f1b);
                        unpk(t2[k],f2a,f2b);unpk(t3[k],f3a,f3b);
                        uint32_t ad=base+(uint32_t)(k*ZT*144);
                        storeRow(ad,f0a,f1a,f2a,f3a);
                        storeRow(ad+144,f0b,f1b,f2b,f3b);
                    }
                } else if(G==1){
                    ull t0[3],t1[3],t2[3],t3[3];
                    pathT<1>(a,b,cf,t0);pathT<3>(a,b,cf,t1);
                    pathT<6>(a,b,cf,t2);pathT<8>(a,b,cf,t3);
#pragma unroll
                    for(int k=0;k<3;k++){
                        float f0a,f0b,f1a,f1b,f2a,f2b,f3a,f3b;
                        unpk(t0[k],f0a,f0b);unpk(t1[k],f1a,f1b);
                        unpk(t2[k],f2a,f2b);unpk(t3[k],f3a,f3b);
                        uint32_t ad=base+(uint32_t)(k*ZT*144);
                        storeRow(ad,f0a,f1a,f2a,f3a);
                        storeRow(ad+144,f0b,f1b,f2b,f3b);
                    }
                } else {
                    ull t0[1],t1[1],t2[1];
                    pathT<0>(a,b,cf,t0);pathT<4>(a,b,cf,t1);pathT<9>(a,b,cf,t2);
                    float f0a,f0b,f1a,f1b,f2a,f2b;
                    unpk(t0[0],f0a,f0b);unpk(t1[0],f1a,f1b);unpk(t2[0],f2a,f2b);
                    storeRow(base,f0a,f1a,f2a,0.f);
                    storeRow(base+144,f0b,f1b,f2b,0.f);
                }
            }
            cpwait0();
            __syncthreads();
#pragma unroll
            for(int ks=0;ks<KS;ks++){
                uint32_t ah[8],al[8],bh[16],bl[16];
                ldsm4(ah,   aAddr+ks*32);
                ldsm4(ah+4, aAddr+2304+ks*32);
                ldsm4(al,   aAddr+18432+ks*32);
                ldsm4(al+4, aAddr+18432+2304+ks*32);
#pragma unroll
                for(int ng=0;ng<4;ng++){
                    ldsm4(bh+4*ng, bAddr+ng*2304+ks*32);
                    ldsm4(bl+4*ng, bAddr+9216+ng*2304+ks*32);
                }
#pragma unroll
                for(int mt=0;mt<2;mt++)
#pragma unroll
                for(int nt=0;nt<8;nt++){
                    int e=nt*2;
                    mma16816(acc[mt][nt], ah+4*mt, bh[e],bh[e+1]);
                    mma16816(acc[mt][nt], ah+4*mt, bl[e],bl[e+1]);
                    mma16816(acc[mt][nt], al+4*mt, bh[e],bh[e+1]);
                }
            }
        }
    }
#pragma unroll
    for(int mt=0;mt<2;mt++)
#pragma unroll
    for(int nt=0;nt<8;nt++)
#pragma unroll
    for(int e=0;e<4;e++){
        int r=wm*32+mt*16+(lane>>2)+(e>>1)*8;
        int w=nt*8+(lane&3)*2+(e&1);
        int k=r/ZT, zl=r%ZT, z=zbase+zl;
        if(k<M3 && z<1024)
            atomicAdd(out+(size_t)(z*64+w)*9+KO+k, acc[mt][nt][e]);
    }
}

// ---------- main kernel ----------
__global__ void __launch_bounds__(128)
tp_mma(const float* x1_0,const float* x2_0,const float* x1_1,const float* x2_1,
       const float* x1_2,const float* x2_2,
       const float* C0,const float* C1,const float* C2,const float* C3,const float* C4,
       const float* C5,const float* C6,const float* C7,const float* C8,const float* C9,
       const float* C10,float* out){
    extern __shared__ char smem[];
    const float* cps[NP]={C0,C1,C2,C3,C4,C5,C6,C7,C8,C9,C10};
    int bid=blockIdx.x;
    if(bid<172)      run<0>(bid,     x1_0,x2_0,x1_1,x2_1,x1_2,x2_2,cps,out,smem);
    else if(bid<272) run<1>(bid-172, x1_0,x2_0,x1_1,x2_1,x1_2,x2_2,cps,out,smem);
    else             run<2>(bid-272, x1_0,x2_0,x1_1,x2_1,x1_2,x2_2,cps,out,smem);
}

// ---------------------------------------------------------------------------
extern "C" void kernel_launch(void* const* d_in, const int* in_sizes, int n_in,
                              void* d_out, int out_size) {
    (void)in_sizes;(void)n_in;
    const float* x1_0=(const float*)d_in[0];
    const float* x2_0=(const float*)d_in[1];
    const float* x1_1=(const float*)d_in[2];
    const float* x2_1=(const float*)d_in[3];
    const float* x1_2=(const float*)d_in[4];
    const float* x2_2=(const float*)d_in[5];
    const float* W   =(const float*)d_in[6];
    float* out=(float*)d_out;

    cudaFuncSetAttribute(tp_mma, cudaFuncAttributeMaxDynamicSharedMemorySize, SMEM_B);

    cudaMemsetAsync(d_out,0,(size_t)out_size*sizeof(float),0);
    prep_W<0><<<512,256>>>(W);
    prep_W<1><<<512,256>>>(W);
    prep_W<2><<<512,256>>>(W);
    tp_mma<<<304,128,SMEM_B>>>(x1_0,x2_0,x1_1,x2_1,x1_2,x2_2,
        (const float*)d_in[7],(const float*)d_in[8],(const float*)d_in[9],
        (const float*)d_in[10],(const float*)d_in[11],(const float*)d_in[12],
        (const float*)d_in[13],(const float*)d_in[14],(const float*)d_in[15],
        (const float*)d_in[16],(const float*)d_in[17],out);
}